// round 10
// baseline (speedup 1.0000x reference)
#include <cuda_runtime.h>
#include <cuda_bf16.h>
#include <math.h>
#include <stdint.h>

// ---------------- problem constants ----------------
#define MAX_NODES 100000
#define MAX_EDGES 2000000
#define D_IN  256
#define D_HID 256
#define D_CLS 64
#define KDIM  256
#define KW    (KDIM / 2)   // packed words per row

// ---------------- scratch (static, no allocs) ----------------
__device__ float    g_h1  [(size_t)MAX_NODES * D_HID];   // GEMM1 out (fp32)
__device__ float    g_h2  [(size_t)MAX_NODES * D_CLS];   // GEMM2 out (fp32)
__device__ uint32_t g_xhi [(size_t)MAX_NODES * KW];      // x split, packed [row][k/2]
__device__ uint32_t g_xlo [(size_t)MAX_NODES * KW];
__device__ uint32_t g_a1hi[(size_t)MAX_NODES * KW];      // agg1 out split
__device__ uint32_t g_a1lo[(size_t)MAX_NODES * KW];
__device__ uint32_t g_w1hi[D_HID * KW], g_w1lo[D_HID * KW];  // W1 split, [n][k/2]
__device__ uint32_t g_w2hi[D_CLS * KW], g_w2lo[D_CLS * KW];  // W2 split
__device__ float    g_dinv[MAX_NODES];
__device__ int      g_cnt [MAX_NODES];
__device__ int      g_off [MAX_NODES];
__device__ int      g_cur [MAX_NODES];
__device__ int      g_srcsort[MAX_EDGES];
__device__ int      g_bsum[1024];
__device__ int      g_boff[1024];

// ---------------- helpers ----------------
__device__ __forceinline__ void split2_bf16(float2 v, uint32_t& hi, uint32_t& lo) {
    __nv_bfloat16 hx = __float2bfloat16(v.x);
    __nv_bfloat16 hy = __float2bfloat16(v.y);
    __nv_bfloat16 lx = __float2bfloat16(v.x - __bfloat162float(hx));
    __nv_bfloat16 ly = __float2bfloat16(v.y - __bfloat162float(hy));
    hi = (uint32_t)__bfloat16_as_ushort(hx) | ((uint32_t)__bfloat16_as_ushort(hy) << 16);
    lo = (uint32_t)__bfloat16_as_ushort(lx) | ((uint32_t)__bfloat16_as_ushort(ly) << 16);
}

__device__ __forceinline__ void cp_async16(uint32_t dst, const void* src, bool pred) {
    int sz = pred ? 16 : 0;
    asm volatile("cp.async.cg.shared.global [%0], [%1], 16, %2;"
                 :: "r"(dst), "l"(src), "r"(sz) : "memory");
}

__device__ __forceinline__ void ldsm_x4(uint32_t r[4], uint32_t addr) {
    asm volatile("ldmatrix.sync.aligned.m8n8.x4.shared.b16 {%0,%1,%2,%3}, [%4];"
                 : "=r"(r[0]), "=r"(r[1]), "=r"(r[2]), "=r"(r[3]) : "r"(addr));
}

__device__ __forceinline__ void mma_bf16(float c[4], const uint32_t a[4],
                                         uint32_t b0, uint32_t b1) {
    asm volatile(
        "mma.sync.aligned.m16n8k16.row.col.f32.bf16.bf16.f32 "
        "{%0,%1,%2,%3}, {%4,%5,%6,%7}, {%8,%9}, {%0,%1,%2,%3};"
        : "+f"(c[0]), "+f"(c[1]), "+f"(c[2]), "+f"(c[3])
        : "r"(a[0]), "r"(a[1]), "r"(a[2]), "r"(a[3]), "r"(b0), "r"(b1));
}

// ---------------- pre-split kernels ----------------
// split x into packed hi/lo word arrays; also zero cnt (first n threads)
__global__ void split_x(const float* __restrict__ x, uint32_t* __restrict__ xhi,
                        uint32_t* __restrict__ xlo, int* __restrict__ cnt,
                        int n, long nw) {
    long i0 = (long)blockIdx.x * blockDim.x + threadIdx.x;
    if (i0 < n) cnt[i0] = 0;
    long stride = (long)gridDim.x * blockDim.x;
    for (long i = i0; i < nw; i += stride) {
        float2 v = ((const float2*)x)[i];
        uint32_t hi, lo;
        split2_bf16(v, hi, lo);
        xhi[i] = hi;
        xlo[i] = lo;
    }
}

// split W1 [256][256] and W2 [256][64] into B-format [n][k/2]
__global__ void split_w(const float* __restrict__ W1, const float* __restrict__ W2,
                        uint32_t* w1hi, uint32_t* w1lo,
                        uint32_t* w2hi, uint32_t* w2lo) {
    int i = blockIdx.x * 256 + threadIdx.x;
    if (i < D_HID * KW) {
        int nn = i >> 7, w = i & (KW - 1);
        float2 v = make_float2(W1[(2 * w) * D_HID + nn], W1[(2 * w + 1) * D_HID + nn]);
        uint32_t hi, lo;
        split2_bf16(v, hi, lo);
        w1hi[i] = hi; w1lo[i] = lo;
    } else if (i < D_HID * KW + D_CLS * KW) {
        int j = i - D_HID * KW;
        int nn = j >> 7, w = j & (KW - 1);
        float2 v = make_float2(W2[(2 * w) * D_CLS + nn], W2[(2 * w + 1) * D_CLS + nn]);
        uint32_t hi, lo;
        split2_bf16(v, hi, lo);
        w2hi[j] = hi; w2lo[j] = lo;
    }
}

// ---------------- CSR build ----------------
__global__ void count_dst(const int* __restrict__ dst, int* cnt, int E) {
    int e = blockIdx.x * blockDim.x + threadIdx.x;
    if (e < E) atomicAdd(&cnt[dst[e]], 1);
}

__global__ void dinv_k(const int* __restrict__ cnt, float* dinv, int n) {
    int i = blockIdx.x * blockDim.x + threadIdx.x;
    if (i < n) dinv[i] = rsqrtf((float)(cnt[i] + 1));
}

__global__ void block_sums(const int* __restrict__ cnt, int* bsum, int n) {
    __shared__ int sh[256];
    int i = blockIdx.x * 256 + threadIdx.x;
    sh[threadIdx.x] = (i < n) ? cnt[i] : 0;
    __syncthreads();
    for (int o = 128; o > 0; o >>= 1) {
        if (threadIdx.x < o) sh[threadIdx.x] += sh[threadIdx.x + o];
        __syncthreads();
    }
    if (threadIdx.x == 0) bsum[blockIdx.x] = sh[0];
}

__global__ void scan_bsums(const int* __restrict__ bsum, int* boff, int nb) {
    __shared__ int sh[1024];
    int t = threadIdx.x;
    int v = (t < nb) ? bsum[t] : 0;
    sh[t] = v;
    __syncthreads();
    for (int o = 1; o < 1024; o <<= 1) {
        int u = (t >= o) ? sh[t - o] : 0;
        __syncthreads();
        sh[t] += u;
        __syncthreads();
    }
    if (t < nb) boff[t] = sh[t] - v;
}

__global__ void scan_final(const int* __restrict__ cnt, const int* __restrict__ boff,
                           int* off, int* cur, int n) {
    __shared__ int sh[256];
    int i = blockIdx.x * 256 + threadIdx.x;
    int v = (i < n) ? cnt[i] : 0;
    sh[threadIdx.x] = v;
    __syncthreads();
    for (int o = 1; o < 256; o <<= 1) {
        int u = (threadIdx.x >= o) ? sh[threadIdx.x - o] : 0;
        __syncthreads();
        sh[threadIdx.x] += u;
        __syncthreads();
    }
    if (i < n) {
        int excl = boff[blockIdx.x] + sh[threadIdx.x] - v;
        off[i] = excl;
        cur[i] = excl;
    }
}

__global__ void place_edges(const int* __restrict__ src, const int* __restrict__ dst,
                            int* cur, int* srcsort, int E) {
    int e = blockIdx.x * blockDim.x + threadIdx.x;
    if (e < E) {
        int d = dst[e];
        int pos = atomicAdd(&cur[d], 1);
        srcsort[pos] = src[e];
    }
}

// ============ 3xBF16 GEMM, pre-split operands, cp.async pipeline ============
// C[m,n] = sum_k A[m,k]*B[k,n] (fp32-class via hi/lo 3-term). No row scale.
__global__ __launch_bounds__(256, 2)
void gemm_bf16x3(const uint32_t* __restrict__ Ahi, const uint32_t* __restrict__ Alo,
                 const uint32_t* __restrict__ Bhi, const uint32_t* __restrict__ Blo,
                 float* __restrict__ C, int M, int N) {
    constexpr int BM = 128, BN = 64, STR = 12;
    constexpr int MT = 2, NT = 4;
    constexpr int ASZ = BM * STR, BSZ = BN * STR;
    constexpr int TILES = KDIM / 16;

    __shared__ alignas(16) uint32_t As_hi[2][ASZ], As_lo[2][ASZ];
    __shared__ alignas(16) uint32_t Bs_hi[2][BSZ], Bs_lo[2][BSZ];

    const int tid  = threadIdx.x;
    const int wid  = tid >> 5;
    const int lane = tid & 31;
    const int g    = lane >> 2;
    const int tig  = lane & 3;
    const int q    = lane >> 3;
    const int lr   = lane & 7;
    const int row0 = blockIdx.y * BM;
    const int col0 = blockIdx.x * BN;
    const int warpM = (wid >> 1) * 32;
    const int warpN = (wid & 1) * 32;

    const uint32_t as_hi_b = (uint32_t)__cvta_generic_to_shared(As_hi);
    const uint32_t as_lo_b = (uint32_t)__cvta_generic_to_shared(As_lo);
    const uint32_t bs_hi_b = (uint32_t)__cvta_generic_to_shared(Bs_hi);
    const uint32_t bs_lo_b = (uint32_t)__cvta_generic_to_shared(Bs_lo);

    // cp.async fixed mapping: A -> thread covers (row, 16B-half); B -> hi/lo by tid>>7
    const int ar = tid >> 1, ahalf = tid & 1;
    const bool a_ok = (row0 + ar) < M;
    const uint32_t a_dst = (uint32_t)((ar * STR + 4 * ahalf) * 4);
    const size_t   a_src = (size_t)(row0 + ar) * KW + 4 * ahalf;
    const int bsel = tid >> 7, bc = tid & 127, bnn = bc >> 1, bhalf = bc & 1;
    const uint32_t b_dst = (uint32_t)((bnn * STR + 4 * bhalf) * 4);
    const size_t   b_src = (size_t)(col0 + bnn) * KW + 4 * bhalf;
    const uint32_t* bsrcp = bsel ? Blo : Bhi;
    const uint32_t  b_dst_base = bsel ? bs_lo_b : bs_hi_b;

    // ldmatrix per-lane byte offsets (within one stage)
    uint32_t a_off[MT], b_off[2];
#pragma unroll
    for (int mt = 0; mt < MT; mt++)
        a_off[mt] = (uint32_t)(((warpM + mt * 16 + (q & 1) * 8 + lr) * STR + (q >> 1) * 4) * 4);
#pragma unroll
    for (int p = 0; p < 2; p++)
        b_off[p] = (uint32_t)(((warpN + (2 * p + (q >> 1)) * 8 + lr) * STR + (q & 1) * 4) * 4);

    float acc[MT][NT][4];
#pragma unroll
    for (int mt = 0; mt < MT; mt++)
#pragma unroll
        for (int nt = 0; nt < NT; nt++)
#pragma unroll
            for (int i = 0; i < 4; i++) acc[mt][nt][i] = 0.0f;

#define ISSUE_TILE(T, S)                                                         \
    do {                                                                         \
        int kw_ = (T) * 8;                                                       \
        cp_async16(as_hi_b + (S) * (ASZ * 4) + a_dst, Ahi + a_src + kw_, a_ok);  \
        cp_async16(as_lo_b + (S) * (ASZ * 4) + a_dst, Alo + a_src + kw_, a_ok);  \
        cp_async16(b_dst_base + (S) * (BSZ * 4) + b_dst, bsrcp + b_src + kw_, true); \
        asm volatile("cp.async.commit_group;" ::: "memory");                     \
    } while (0)

    ISSUE_TILE(0, 0);

#pragma unroll 1
    for (int t = 0; t < TILES; t++) {
        const int s = t & 1;
        if (t + 1 < TILES) {
            ISSUE_TILE(t + 1, (t + 1) & 1);
            asm volatile("cp.async.wait_group 1;" ::: "memory");
        } else {
            asm volatile("cp.async.wait_group 0;" ::: "memory");
        }
        __syncthreads();

        uint32_t a_hi[MT][4], a_lo[MT][4];
#pragma unroll
        for (int mt = 0; mt < MT; mt++) {
            ldsm_x4(a_hi[mt], as_hi_b + s * (ASZ * 4) + a_off[mt]);
            ldsm_x4(a_lo[mt], as_lo_b + s * (ASZ * 4) + a_off[mt]);
        }
        uint32_t b_hi[2][4], b_lo[2][4];
#pragma unroll
        for (int p = 0; p < 2; p++) {
            ldsm_x4(b_hi[p], bs_hi_b + s * (BSZ * 4) + b_off[p]);
            ldsm_x4(b_lo[p], bs_lo_b + s * (BSZ * 4) + b_off[p]);
        }

#pragma unroll
        for (int mt = 0; mt < MT; mt++)
#pragma unroll
            for (int nt = 0; nt < NT; nt++) {
                int p = nt >> 1, o = (nt & 1) * 2;
                mma_bf16(acc[mt][nt], a_hi[mt], b_lo[p][o], b_lo[p][o + 1]);
                mma_bf16(acc[mt][nt], a_lo[mt], b_hi[p][o], b_hi[p][o + 1]);
                mma_bf16(acc[mt][nt], a_hi[mt], b_hi[p][o], b_hi[p][o + 1]);
            }
        __syncthreads();
    }
#undef ISSUE_TILE

#pragma unroll
    for (int mt = 0; mt < MT; mt++) {
        int r1 = row0 + warpM + mt * 16 + g;
        int r2 = r1 + 8;
#pragma unroll
        for (int nt = 0; nt < NT; nt++) {
            int cc = col0 + warpN + nt * 8 + 2 * tig;
            if (r1 < M)
                *(float2*)(C + (size_t)r1 * N + cc) = make_float2(acc[mt][nt][0], acc[mt][nt][1]);
            if (r2 < M)
                *(float2*)(C + (size_t)r2 * N + cc) = make_float2(acc[mt][nt][2], acc[mt][nt][3]);
        }
    }
}

// ====== layer-1 aggregate: per-edge dinv scaling, split-bf16 output ======
// a = h[d]*dinv[d] + sum h[s]*dinv[s]; r = relu(a*dinv[d] + b1); write split words.
__global__ void agg1_kernel(const float* __restrict__ h,
                            const int* __restrict__ srcsort,
                            const int* __restrict__ off,
                            const float* __restrict__ dinv,
                            const float* __restrict__ b1,
                            uint32_t* __restrict__ a1hi, uint32_t* __restrict__ a1lo,
                            int n, int E) {
    int node = blockIdx.x * (blockDim.x >> 5) + (threadIdx.x >> 5);
    if (node >= n) return;
    int lane = threadIdx.x & 31;

    float di = dinv[node];
    const float4* hp = (const float4*)(h + (size_t)node * D_HID);
    float4 v0 = __ldg(hp + lane);
    float4 v1 = __ldg(hp + lane + 32);
    float4 a0 = make_float4(v0.x * di, v0.y * di, v0.z * di, v0.w * di);
    float4 a1 = make_float4(v1.x * di, v1.y * di, v1.z * di, v1.w * di);

    int e0 = off[node];
    int e1 = (node + 1 < n) ? off[node + 1] : E;
    for (int e = e0; e < e1; e++) {
        int s = srcsort[e];
        float ds = __ldg(dinv + s);
        const float4* sp = (const float4*)(h + (size_t)s * D_HID);
        float4 u0 = __ldg(sp + lane);
        float4 u1 = __ldg(sp + lane + 32);
        a0.x = fmaf(u0.x, ds, a0.x); a0.y = fmaf(u0.y, ds, a0.y);
        a0.z = fmaf(u0.z, ds, a0.z); a0.w = fmaf(u0.w, ds, a0.w);
        a1.x = fmaf(u1.x, ds, a1.x); a1.y = fmaf(u1.y, ds, a1.y);
        a1.z = fmaf(u1.z, ds, a1.z); a1.w = fmaf(u1.w, ds, a1.w);
    }

    const float4* bb = (const float4*)b1;
    float4 c0 = __ldg(bb + lane);
    float4 c1 = __ldg(bb + lane + 32);
    float4 r0, r1;
    r0.x = fmaxf(fmaf(a0.x, di, c0.x), 0.0f);
    r0.y = fmaxf(fmaf(a0.y, di, c0.y), 0.0f);
    r0.z = fmaxf(fmaf(a0.z, di, c0.z), 0.0f);
    r0.w = fmaxf(fmaf(a0.w, di, c0.w), 0.0f);
    r1.x = fmaxf(fmaf(a1.x, di, c1.x), 0.0f);
    r1.y = fmaxf(fmaf(a1.y, di, c1.y), 0.0f);
    r1.z = fmaxf(fmaf(a1.z, di, c1.z), 0.0f);
    r1.w = fmaxf(fmaf(a1.w, di, c1.w), 0.0f);

    uint32_t h0a, l0a, h0b, l0b, h1a, l1a, h1b, l1b;
    split2_bf16(make_float2(r0.x, r0.y), h0a, l0a);
    split2_bf16(make_float2(r0.z, r0.w), h0b, l0b);
    split2_bf16(make_float2(r1.x, r1.y), h1a, l1a);
    split2_bf16(make_float2(r1.z, r1.w), h1b, l1b);
    uint2* ophi = (uint2*)(a1hi + (size_t)node * KW);
    uint2* oplo = (uint2*)(a1lo + (size_t)node * KW);
    ophi[lane]      = make_uint2(h0a, h0b);
    ophi[lane + 32] = make_uint2(h1a, h1b);
    oplo[lane]      = make_uint2(l0a, l0b);
    oplo[lane + 32] = make_uint2(l1a, l1b);
}

// ====== layer-2 aggregate: per-edge dinv scaling + bias + log_softmax ======
__global__ void agg2_kernel(const float* __restrict__ h,
                            const int* __restrict__ srcsort,
                            const int* __restrict__ off,
                            const float* __restrict__ dinv,
                            const float* __restrict__ b2,
                            float* __restrict__ out, int n, int E) {
    int node = blockIdx.x * (blockDim.x >> 5) + (threadIdx.x >> 5);
    if (node >= n) return;
    int lane = threadIdx.x & 31;

    float di = dinv[node];
    const float2* hp = (const float2*)(h + (size_t)node * D_CLS);
    float2 u = __ldg(hp + lane);
    float2 a = make_float2(u.x * di, u.y * di);

    int e0 = off[node];
    int e1 = (node + 1 < n) ? off[node + 1] : E;
    for (int e = e0; e < e1; e++) {
        int s = srcsort[e];
        float ds = __ldg(dinv + s);
        float2 v = __ldg(((const float2*)(h + (size_t)s * D_CLS)) + lane);
        a.x = fmaf(v.x, ds, a.x);
        a.y = fmaf(v.y, ds, a.y);
    }

    float v0 = fmaf(a.x, di, __ldg(b2 + 2 * lane));
    float v1 = fmaf(a.y, di, __ldg(b2 + 2 * lane + 1));

    float m = fmaxf(v0, v1);
#pragma unroll
    for (int o = 16; o > 0; o >>= 1) m = fmaxf(m, __shfl_xor_sync(0xFFFFFFFFu, m, o));
    float s = __expf(v0 - m) + __expf(v1 - m);
#pragma unroll
    for (int o = 16; o > 0; o >>= 1) s += __shfl_xor_sync(0xFFFFFFFFu, s, o);
    float lse = m + __logf(s);

    float2* op = (float2*)(out + (size_t)node * D_CLS);
    op[lane] = make_float2(v0 - lse, v1 - lse);
}

extern "C" void kernel_launch(void* const* d_in, const int* in_sizes, int n_in,
                              void* d_out, int out_size) {
    const float* x   = (const float*)d_in[0];
    const int*   ei  = (const int*)d_in[1];   // JAX int64 request silently -> int32
    const float* W1  = (const float*)d_in[2];
    const float* b1  = (const float*)d_in[3];
    const float* W2  = (const float*)d_in[4];
    const float* b2  = (const float*)d_in[5];
    float*       out = (float*)d_out;

    const int n = in_sizes[0] / D_IN;
    const int E = in_sizes[1] / 2;
    const int* src = ei;
    const int* dst = ei + E;

    float *h1, *h2, *dinv;
    uint32_t *xhi, *xlo, *a1hi, *a1lo, *w1hi, *w1lo, *w2hi, *w2lo;
    int *cnt, *off, *cur, *srcsort, *bsum, *boff;
    cudaGetSymbolAddress((void**)&h1,   g_h1);
    cudaGetSymbolAddress((void**)&h2,   g_h2);
    cudaGetSymbolAddress((void**)&xhi,  g_xhi);
    cudaGetSymbolAddress((void**)&xlo,  g_xlo);
    cudaGetSymbolAddress((void**)&a1hi, g_a1hi);
    cudaGetSymbolAddress((void**)&a1lo, g_a1lo);
    cudaGetSymbolAddress((void**)&w1hi, g_w1hi);
    cudaGetSymbolAddress((void**)&w1lo, g_w1lo);
    cudaGetSymbolAddress((void**)&w2hi, g_w2hi);
    cudaGetSymbolAddress((void**)&w2lo, g_w2lo);
    cudaGetSymbolAddress((void**)&dinv, g_dinv);
    cudaGetSymbolAddress((void**)&cnt,  g_cnt);
    cudaGetSymbolAddress((void**)&off,  g_off);
    cudaGetSymbolAddress((void**)&cur,  g_cur);
    cudaGetSymbolAddress((void**)&srcsort, g_srcsort);
    cudaGetSymbolAddress((void**)&bsum, g_bsum);
    cudaGetSymbolAddress((void**)&boff, g_boff);

    const int NB = (n + 255) / 256;   // <= 1024
    const int MB = (n + 127) / 128;
    const long nwords = (long)n * KW;

    // 1: split x (+ zero cnt), 2: split weights, 3: degree count
    split_x<<<2048, 256>>>(x, xhi, xlo, cnt, n, nwords);
    split_w<<<(D_HID * KW + D_CLS * KW + 255) / 256, 256>>>(W1, W2, w1hi, w1lo, w2hi, w2lo);
    count_dst<<<(E + 255) / 256, 256>>>(dst, cnt, E);

    // 4: GEMM1 (profiler capture slot): h1 = x @ W1
    gemm_bf16x3<<<dim3(D_HID / 64, MB), 256>>>(xhi, xlo, w1hi, w1lo, h1, n, D_HID);

    // dinv + CSR
    dinv_k     <<<NB, 256>>>(cnt, dinv, n);
    block_sums <<<NB, 256>>>(cnt, bsum, n);
    scan_bsums <<<1, 1024>>>(bsum, boff, NB);
    scan_final <<<NB, 256>>>(cnt, boff, off, cur, n);
    place_edges<<<(E + 255) / 256, 256>>>(src, dst, cur, srcsort, E);

    // agg1: normalize+aggregate+bias+relu, emit split bf16
    agg1_kernel<<<(n + 7) / 8, 256>>>(h1, srcsort, off, dinv, b1, a1hi, a1lo, n, E);

    // GEMM2: h2 = agg1 @ W2
    gemm_bf16x3<<<dim3(D_CLS / 64, MB), 256>>>(a1hi, a1lo, w2hi, w2lo, h2, n, D_CLS);

    // agg2: normalize+aggregate+bias+log_softmax
    agg2_kernel<<<(n + 7) / 8, 256>>>(h2, srcsort, off, dinv, b2, out, n, E);
}

// round 11
// speedup vs baseline: 1.0116x; 1.0116x over previous
#include <cuda_runtime.h>
#include <cuda_bf16.h>
#include <math.h>
#include <stdint.h>

// ---------------- problem constants ----------------
#define MAX_NODES 100000
#define MAX_EDGES 2000000
#define D_IN  256
#define D_HID 256
#define D_CLS 64
#define KDIM  256
#define KW    (KDIM / 2)   // packed words per row

// ---------------- scratch (static, no allocs) ----------------
__device__ float    g_h1  [(size_t)MAX_NODES * D_HID];
__device__ float    g_h2  [(size_t)MAX_NODES * D_CLS];
__device__ uint32_t g_xhi [(size_t)MAX_NODES * KW];
__device__ uint32_t g_xlo [(size_t)MAX_NODES * KW];
__device__ uint32_t g_a1hi[(size_t)MAX_NODES * KW];
__device__ uint32_t g_a1lo[(size_t)MAX_NODES * KW];
__device__ uint32_t g_w1hi[D_HID * KW], g_w1lo[D_HID * KW];
__device__ uint32_t g_w2hi[D_CLS * KW], g_w2lo[D_CLS * KW];
__device__ float    g_dinv[MAX_NODES];
__device__ int      g_cnt [MAX_NODES];
__device__ int      g_off [MAX_NODES];
__device__ int      g_cur [MAX_NODES];
__device__ int      g_srcsort[MAX_EDGES];
__device__ int      g_bsum[1024];
__device__ int      g_boff[1024];

// ---------------- helpers ----------------
__device__ __forceinline__ void split2_bf16(float2 v, uint32_t& hi, uint32_t& lo) {
    __nv_bfloat16 hx = __float2bfloat16(v.x);
    __nv_bfloat16 hy = __float2bfloat16(v.y);
    __nv_bfloat16 lx = __float2bfloat16(v.x - __bfloat162float(hx));
    __nv_bfloat16 ly = __float2bfloat16(v.y - __bfloat162float(hy));
    hi = (uint32_t)__bfloat16_as_ushort(hx) | ((uint32_t)__bfloat16_as_ushort(hy) << 16);
    lo = (uint32_t)__bfloat16_as_ushort(lx) | ((uint32_t)__bfloat16_as_ushort(ly) << 16);
}

__device__ __forceinline__ void cp_async16(uint32_t dst, const void* src, bool pred) {
    int sz = pred ? 16 : 0;
    asm volatile("cp.async.cg.shared.global [%0], [%1], 16, %2;"
                 :: "r"(dst), "l"(src), "r"(sz) : "memory");
}

__device__ __forceinline__ void ldsm_x4(uint32_t r[4], uint32_t addr) {
    asm volatile("ldmatrix.sync.aligned.m8n8.x4.shared.b16 {%0,%1,%2,%3}, [%4];"
                 : "=r"(r[0]), "=r"(r[1]), "=r"(r[2]), "=r"(r[3]) : "r"(addr));
}

__device__ __forceinline__ void mma_bf16(float c[4], const uint32_t a[4],
                                         uint32_t b0, uint32_t b1) {
    asm volatile(
        "mma.sync.aligned.m16n8k16.row.col.f32.bf16.bf16.f32 "
        "{%0,%1,%2,%3}, {%4,%5,%6,%7}, {%8,%9}, {%0,%1,%2,%3};"
        : "+f"(c[0]), "+f"(c[1]), "+f"(c[2]), "+f"(c[3])
        : "r"(a[0]), "r"(a[1]), "r"(a[2]), "r"(a[3]), "r"(b0), "r"(b1));
}

// ---------------- pre-split kernels ----------------
__global__ void split_x(const float* __restrict__ x, uint32_t* __restrict__ xhi,
                        uint32_t* __restrict__ xlo, int* __restrict__ cnt,
                        int n, long nw) {
    long i0 = (long)blockIdx.x * blockDim.x + threadIdx.x;
    if (i0 < n) cnt[i0] = 0;
    long stride = (long)gridDim.x * blockDim.x;
    for (long i = i0; i < nw; i += stride) {
        float2 v = ((const float2*)x)[i];
        uint32_t hi, lo;
        split2_bf16(v, hi, lo);
        xhi[i] = hi;
        xlo[i] = lo;
    }
}

__global__ void split_w(const float* __restrict__ W1, const float* __restrict__ W2,
                        uint32_t* w1hi, uint32_t* w1lo,
                        uint32_t* w2hi, uint32_t* w2lo) {
    int i = blockIdx.x * 256 + threadIdx.x;
    if (i < D_HID * KW) {
        int nn = i >> 7, w = i & (KW - 1);
        float2 v = make_float2(W1[(2 * w) * D_HID + nn], W1[(2 * w + 1) * D_HID + nn]);
        uint32_t hi, lo;
        split2_bf16(v, hi, lo);
        w1hi[i] = hi; w1lo[i] = lo;
    } else if (i < D_HID * KW + D_CLS * KW) {
        int j = i - D_HID * KW;
        int nn = j >> 7, w = j & (KW - 1);
        float2 v = make_float2(W2[(2 * w) * D_CLS + nn], W2[(2 * w + 1) * D_CLS + nn]);
        uint32_t hi, lo;
        split2_bf16(v, hi, lo);
        w2hi[j] = hi; w2lo[j] = lo;
    }
}

// ---------------- CSR build ----------------
__global__ void count_dst(const int* __restrict__ dst, int* cnt, int E) {
    int e = blockIdx.x * blockDim.x + threadIdx.x;
    if (e < E) atomicAdd(&cnt[dst[e]], 1);
}

__global__ void dinv_k(const int* __restrict__ cnt, float* dinv, int n) {
    int i = blockIdx.x * blockDim.x + threadIdx.x;
    if (i < n) dinv[i] = rsqrtf((float)(cnt[i] + 1));
}

__global__ void block_sums(const int* __restrict__ cnt, int* bsum, int n) {
    __shared__ int sh[256];
    int i = blockIdx.x * 256 + threadIdx.x;
    sh[threadIdx.x] = (i < n) ? cnt[i] : 0;
    __syncthreads();
    for (int o = 128; o > 0; o >>= 1) {
        if (threadIdx.x < o) sh[threadIdx.x] += sh[threadIdx.x + o];
        __syncthreads();
    }
    if (threadIdx.x == 0) bsum[blockIdx.x] = sh[0];
}

__global__ void scan_bsums(const int* __restrict__ bsum, int* boff, int nb) {
    __shared__ int sh[1024];
    int t = threadIdx.x;
    int v = (t < nb) ? bsum[t] : 0;
    sh[t] = v;
    __syncthreads();
    for (int o = 1; o < 1024; o <<= 1) {
        int u = (t >= o) ? sh[t - o] : 0;
        __syncthreads();
        sh[t] += u;
        __syncthreads();
    }
    if (t < nb) boff[t] = sh[t] - v;
}

__global__ void scan_final(const int* __restrict__ cnt, const int* __restrict__ boff,
                           int* off, int* cur, int n) {
    __shared__ int sh[256];
    int i = blockIdx.x * 256 + threadIdx.x;
    int v = (i < n) ? cnt[i] : 0;
    sh[threadIdx.x] = v;
    __syncthreads();
    for (int o = 1; o < 256; o <<= 1) {
        int u = (threadIdx.x >= o) ? sh[threadIdx.x - o] : 0;
        __syncthreads();
        sh[threadIdx.x] += u;
        __syncthreads();
    }
    if (i < n) {
        int excl = boff[blockIdx.x] + sh[threadIdx.x] - v;
        off[i] = excl;
        cur[i] = excl;
    }
}

__global__ void place_edges(const int* __restrict__ src, const int* __restrict__ dst,
                            int* cur, int* srcsort, int E) {
    int e = blockIdx.x * blockDim.x + threadIdx.x;
    if (e < E) {
        int d = dst[e];
        int pos = atomicAdd(&cur[d], 1);
        srcsort[pos] = src[e];
    }
}

// ====== 3xBF16 GEMM, pre-split operands, 4-stage cp.async pipeline ======
// Dynamic smem layout per stage: [A_hi(ASZ) | A_lo(ASZ) | B_hi(BSZ) | B_lo(BSZ)]
__global__ __launch_bounds__(256)
void gemm_bf16x3(const uint32_t* __restrict__ Ahi, const uint32_t* __restrict__ Alo,
                 const uint32_t* __restrict__ Bhi, const uint32_t* __restrict__ Blo,
                 float* __restrict__ C, int M, int N) {
    constexpr int BM = 128, BN = 64, STR = 12;
    constexpr int MT = 2, NT = 4;
    constexpr int ASZ = BM * STR, BSZ = BN * STR;          // words
    constexpr int TILES = KDIM / 16;
    constexpr int STAGES = 4;
    constexpr uint32_t STAGE_B = (uint32_t)(2 * ASZ + 2 * BSZ) * 4;  // 18432 bytes

    extern __shared__ __align__(16) uint32_t smem_dyn[];

    const int tid  = threadIdx.x;
    const int wid  = tid >> 5;
    const int lane = tid & 31;
    const int g    = lane >> 2;
    const int tig  = lane & 3;
    const int q    = lane >> 3;
    const int lr   = lane & 7;
    const int row0 = blockIdx.y * BM;
    const int col0 = blockIdx.x * BN;
    const int warpM = (wid >> 1) * 32;
    const int warpN = (wid & 1) * 32;

    const uint32_t base = (uint32_t)__cvta_generic_to_shared(smem_dyn);
    const uint32_t a_hi_b = base;
    const uint32_t a_lo_b = base + (uint32_t)ASZ * 4;
    const uint32_t b_hi_b = base + (uint32_t)(2 * ASZ) * 4;
    const uint32_t b_lo_b = base + (uint32_t)(2 * ASZ + BSZ) * 4;

    // cp.async fixed mapping: A -> thread covers (row, 16B-half); B -> hi/lo by tid>>7
    const int ar = tid >> 1, ahalf = tid & 1;
    const bool a_ok = (row0 + ar) < M;
    const uint32_t a_dst = (uint32_t)((ar * STR + 4 * ahalf) * 4);
    const size_t   a_src = (size_t)(row0 + ar) * KW + 4 * ahalf;
    const int bsel = tid >> 7, bc = tid & 127, bnn = bc >> 1, bhalf = bc & 1;
    const uint32_t b_dst = (uint32_t)((bnn * STR + 4 * bhalf) * 4);
    const size_t   b_src = (size_t)(col0 + bnn) * KW + 4 * bhalf;
    const uint32_t* bsrcp = bsel ? Blo : Bhi;
    const uint32_t  b_dst_sel = bsel ? b_lo_b : b_hi_b;

    // ldmatrix per-lane byte offsets within a stage
    uint32_t a_off[MT], b_off[2];
#pragma unroll
    for (int mt = 0; mt < MT; mt++)
        a_off[mt] = (uint32_t)(((warpM + mt * 16 + (q & 1) * 8 + lr) * STR + (q >> 1) * 4) * 4);
#pragma unroll
    for (int p = 0; p < 2; p++)
        b_off[p] = (uint32_t)(((warpN + (2 * p + (q >> 1)) * 8 + lr) * STR + (q & 1) * 4) * 4);

    float acc[MT][NT][4];
#pragma unroll
    for (int mt = 0; mt < MT; mt++)
#pragma unroll
        for (int nt = 0; nt < NT; nt++)
#pragma unroll
            for (int i = 0; i < 4; i++) acc[mt][nt][i] = 0.0f;

#define ISSUE_TILE(T)                                                              \
    do {                                                                           \
        uint32_t so = (uint32_t)((T) & (STAGES - 1)) * STAGE_B;                    \
        int kw_ = (T) * 8;                                                         \
        cp_async16(a_hi_b + so + a_dst, Ahi + a_src + kw_, a_ok);                  \
        cp_async16(a_lo_b + so + a_dst, Alo + a_src + kw_, a_ok);                  \
        cp_async16(b_dst_sel + so + b_dst, bsrcp + b_src + kw_, true);             \
    } while (0)

    // prologue: stages 0..2 in flight
#pragma unroll
    for (int p = 0; p < STAGES - 1; p++) {
        ISSUE_TILE(p);
        asm volatile("cp.async.commit_group;" ::: "memory");
    }

#pragma unroll 1
    for (int t = 0; t < TILES; t++) {
        if (t + STAGES - 1 < TILES) ISSUE_TILE(t + STAGES - 1);
        asm volatile("cp.async.commit_group;" ::: "memory");   // possibly empty
        asm volatile("cp.async.wait_group %0;" :: "n"(STAGES - 1) : "memory");
        __syncthreads();

        const uint32_t so = (uint32_t)(t & (STAGES - 1)) * STAGE_B;
        uint32_t a_hi[MT][4], a_lo[MT][4];
#pragma unroll
        for (int mt = 0; mt < MT; mt++) {
            ldsm_x4(a_hi[mt], a_hi_b + so + a_off[mt]);
            ldsm_x4(a_lo[mt], a_lo_b + so + a_off[mt]);
        }
        uint32_t b_hi[2][4], b_lo[2][4];
#pragma unroll
        for (int p = 0; p < 2; p++) {
            ldsm_x4(b_hi[p], b_hi_b + so + b_off[p]);
            ldsm_x4(b_lo[p], b_lo_b + so + b_off[p]);
        }

#pragma unroll
        for (int mt = 0; mt < MT; mt++)
#pragma unroll
            for (int nt = 0; nt < NT; nt++) {
                int p = nt >> 1, o = (nt & 1) * 2;
                mma_bf16(acc[mt][nt], a_hi[mt], b_lo[p][o], b_lo[p][o + 1]);
                mma_bf16(acc[mt][nt], a_lo[mt], b_hi[p][o], b_hi[p][o + 1]);
                mma_bf16(acc[mt][nt], a_hi[mt], b_hi[p][o], b_hi[p][o + 1]);
            }
        __syncthreads();   // all reads of this stage done before it is refilled
    }
#undef ISSUE_TILE

#pragma unroll
    for (int mt = 0; mt < MT; mt++) {
        int r1 = row0 + warpM + mt * 16 + g;
        int r2 = r1 + 8;
#pragma unroll
        for (int nt = 0; nt < NT; nt++) {
            int cc = col0 + warpN + nt * 8 + 2 * tig;
            if (r1 < M)
                *(float2*)(C + (size_t)r1 * N + cc) = make_float2(acc[mt][nt][0], acc[mt][nt][1]);
            if (r2 < M)
                *(float2*)(C + (size_t)r2 * N + cc) = make_float2(acc[mt][nt][2], acc[mt][nt][3]);
        }
    }
}

// ====== layer-1 aggregate ======
__global__ void agg1_kernel(const float* __restrict__ h,
                            const int* __restrict__ srcsort,
                            const int* __restrict__ off,
                            const float* __restrict__ dinv,
                            const float* __restrict__ b1,
                            uint32_t* __restrict__ a1hi, uint32_t* __restrict__ a1lo,
                            int n, int E) {
    int node = blockIdx.x * (blockDim.x >> 5) + (threadIdx.x >> 5);
    if (node >= n) return;
    int lane = threadIdx.x & 31;

    float di = dinv[node];
    const float4* hp = (const float4*)(h + (size_t)node * D_HID);
    float4 v0 = __ldg(hp + lane);
    float4 v1 = __ldg(hp + lane + 32);
    float4 a0 = make_float4(v0.x * di, v0.y * di, v0.z * di, v0.w * di);
    float4 a1 = make_float4(v1.x * di, v1.y * di, v1.z * di, v1.w * di);

    int e0 = off[node];
    int e1 = (node + 1 < n) ? off[node + 1] : E;
    for (int e = e0; e < e1; e++) {
        int s = srcsort[e];
        float ds = __ldg(dinv + s);
        const float4* sp = (const float4*)(h + (size_t)s * D_HID);
        float4 u0 = __ldg(sp + lane);
        float4 u1 = __ldg(sp + lane + 32);
        a0.x = fmaf(u0.x, ds, a0.x); a0.y = fmaf(u0.y, ds, a0.y);
        a0.z = fmaf(u0.z, ds, a0.z); a0.w = fmaf(u0.w, ds, a0.w);
        a1.x = fmaf(u1.x, ds, a1.x); a1.y = fmaf(u1.y, ds, a1.y);
        a1.z = fmaf(u1.z, ds, a1.z); a1.w = fmaf(u1.w, ds, a1.w);
    }

    const float4* bb = (const float4*)b1;
    float4 c0 = __ldg(bb + lane);
    float4 c1 = __ldg(bb + lane + 32);
    float4 r0, r1;
    r0.x = fmaxf(fmaf(a0.x, di, c0.x), 0.0f);
    r0.y = fmaxf(fmaf(a0.y, di, c0.y), 0.0f);
    r0.z = fmaxf(fmaf(a0.z, di, c0.z), 0.0f);
    r0.w = fmaxf(fmaf(a0.w, di, c0.w), 0.0f);
    r1.x = fmaxf(fmaf(a1.x, di, c1.x), 0.0f);
    r1.y = fmaxf(fmaf(a1.y, di, c1.y), 0.0f);
    r1.z = fmaxf(fmaf(a1.z, di, c1.z), 0.0f);
    r1.w = fmaxf(fmaf(a1.w, di, c1.w), 0.0f);

    uint32_t h0a, l0a, h0b, l0b, h1a, l1a, h1b, l1b;
    split2_bf16(make_float2(r0.x, r0.y), h0a, l0a);
    split2_bf16(make_float2(r0.z, r0.w), h0b, l0b);
    split2_bf16(make_float2(r1.x, r1.y), h1a, l1a);
    split2_bf16(make_float2(r1.z, r1.w), h1b, l1b);
    uint2* ophi = (uint2*)(a1hi + (size_t)node * KW);
    uint2* oplo = (uint2*)(a1lo + (size_t)node * KW);
    ophi[lane]      = make_uint2(h0a, h0b);
    ophi[lane + 32] = make_uint2(h1a, h1b);
    oplo[lane]      = make_uint2(l0a, l0b);
    oplo[lane + 32] = make_uint2(l1a, l1b);
}

// ====== layer-2 aggregate ======
__global__ void agg2_kernel(const float* __restrict__ h,
                            const int* __restrict__ srcsort,
                            const int* __restrict__ off,
                            const float* __restrict__ dinv,
                            const float* __restrict__ b2,
                            float* __restrict__ out, int n, int E) {
    int node = blockIdx.x * (blockDim.x >> 5) + (threadIdx.x >> 5);
    if (node >= n) return;
    int lane = threadIdx.x & 31;

    float di = dinv[node];
    const float2* hp = (const float2*)(h + (size_t)node * D_CLS);
    float2 u = __ldg(hp + lane);
    float2 a = make_float2(u.x * di, u.y * di);

    int e0 = off[node];
    int e1 = (node + 1 < n) ? off[node + 1] : E;
    for (int e = e0; e < e1; e++) {
        int s = srcsort[e];
        float ds = __ldg(dinv + s);
        float2 v = __ldg(((const float2*)(h + (size_t)s * D_CLS)) + lane);
        a.x = fmaf(v.x, ds, a.x);
        a.y = fmaf(v.y, ds, a.y);
    }

    float v0 = fmaf(a.x, di, __ldg(b2 + 2 * lane));
    float v1 = fmaf(a.y, di, __ldg(b2 + 2 * lane + 1));

    float m = fmaxf(v0, v1);
#pragma unroll
    for (int o = 16; o > 0; o >>= 1) m = fmaxf(m, __shfl_xor_sync(0xFFFFFFFFu, m, o));
    float s = __expf(v0 - m) + __expf(v1 - m);
#pragma unroll
    for (int o = 16; o > 0; o >>= 1) s += __shfl_xor_sync(0xFFFFFFFFu, s, o);
    float lse = m + __logf(s);

    float2* op = (float2*)(out + (size_t)node * D_CLS);
    op[lane] = make_float2(v0 - lse, v1 - lse);
}

extern "C" void kernel_launch(void* const* d_in, const int* in_sizes, int n_in,
                              void* d_out, int out_size) {
    const float* x   = (const float*)d_in[0];
    const int*   ei  = (const int*)d_in[1];   // JAX int64 request silently -> int32
    const float* W1  = (const float*)d_in[2];
    const float* b1  = (const float*)d_in[3];
    const float* W2  = (const float*)d_in[4];
    const float* b2  = (const float*)d_in[5];
    float*       out = (float*)d_out;

    const int n = in_sizes[0] / D_IN;
    const int E = in_sizes[1] / 2;
    const int* src = ei;
    const int* dst = ei + E;

    float *h1, *h2, *dinv;
    uint32_t *xhi, *xlo, *a1hi, *a1lo, *w1hi, *w1lo, *w2hi, *w2lo;
    int *cnt, *off, *cur, *srcsort, *bsum, *boff;
    cudaGetSymbolAddress((void**)&h1,   g_h1);
    cudaGetSymbolAddress((void**)&h2,   g_h2);
    cudaGetSymbolAddress((void**)&xhi,  g_xhi);
    cudaGetSymbolAddress((void**)&xlo,  g_xlo);
    cudaGetSymbolAddress((void**)&a1hi, g_a1hi);
    cudaGetSymbolAddress((void**)&a1lo, g_a1lo);
    cudaGetSymbolAddress((void**)&w1hi, g_w1hi);
    cudaGetSymbolAddress((void**)&w1lo, g_w1lo);
    cudaGetSymbolAddress((void**)&w2hi, g_w2hi);
    cudaGetSymbolAddress((void**)&w2lo, g_w2lo);
    cudaGetSymbolAddress((void**)&dinv, g_dinv);
    cudaGetSymbolAddress((void**)&cnt,  g_cnt);
    cudaGetSymbolAddress((void**)&off,  g_off);
    cudaGetSymbolAddress((void**)&cur,  g_cur);
    cudaGetSymbolAddress((void**)&srcsort, g_srcsort);
    cudaGetSymbolAddress((void**)&bsum, g_bsum);
    cudaGetSymbolAddress((void**)&boff, g_boff);

    const int NB = (n + 255) / 256;   // <= 1024
    const int MB = (n + 127) / 128;
    const long nwords = (long)n * KW;

    // 4-stage pipeline needs 72KB dynamic smem
    const int SMEM_GEMM = 4 * (2 * 128 * 12 + 2 * 64 * 12) * 4;   // 73728
    cudaFuncSetAttribute(gemm_bf16x3, cudaFuncAttributeMaxDynamicSharedMemorySize, SMEM_GEMM);

    // 1: split x (+ zero cnt), 2: split weights, 3: degree count
    split_x<<<2048, 256>>>(x, xhi, xlo, cnt, n, nwords);
    split_w<<<(D_HID * KW + D_CLS * KW + 255) / 256, 256>>>(W1, W2, w1hi, w1lo, w2hi, w2lo);
    count_dst<<<(E + 255) / 256, 256>>>(dst, cnt, E);

    // 4: GEMM1 (profiler capture slot): h1 = x @ W1
    gemm_bf16x3<<<dim3(D_HID / 64, MB), 256, SMEM_GEMM>>>(xhi, xlo, w1hi, w1lo, h1, n, D_HID);

    // dinv + CSR
    dinv_k     <<<NB, 256>>>(cnt, dinv, n);
    block_sums <<<NB, 256>>>(cnt, bsum, n);
    scan_bsums <<<1, 1024>>>(bsum, boff, NB);
    scan_final <<<NB, 256>>>(cnt, boff, off, cur, n);
    place_edges<<<(E + 255) / 256, 256>>>(src, dst, cur, srcsort, E);

    // agg1: normalize+aggregate+bias+relu, emit split bf16
    agg1_kernel<<<(n + 7) / 8, 256>>>(h1, srcsort, off, dinv, b1, a1hi, a1lo, n, E);

    // GEMM2: h2 = agg1 @ W2
    gemm_bf16x3<<<dim3(D_CLS / 64, MB), 256, SMEM_GEMM>>>(a1hi, a1lo, w2hi, w2lo, h2, n, D_CLS);

    // agg2: normalize+aggregate+bias+log_softmax
    agg2_kernel<<<(n + 7) / 8, 256>>>(h2, srcsort, off, dinv, b2, out, n, E);
}

// round 12
// speedup vs baseline: 1.0828x; 1.0704x over previous
#include <cuda_runtime.h>
#include <cuda_bf16.h>
#include <math.h>
#include <stdint.h>

// ---------------- problem constants ----------------
#define MAX_NODES 100000
#define MAX_EDGES 2000000
#define D_IN  256
#define D_HID 256
#define D_CLS 64
#define KDIM  256
#define KW    (KDIM / 2)   // packed words per row

// ---------------- scratch (static, no allocs) ----------------
__device__ float    g_h1  [(size_t)MAX_NODES * D_HID];
__device__ float    g_h2  [(size_t)MAX_NODES * D_CLS];
__device__ uint32_t g_xhi [(size_t)MAX_NODES * KW];
__device__ uint32_t g_xlo [(size_t)MAX_NODES * KW];
__device__ uint32_t g_a1hi[(size_t)MAX_NODES * KW];
__device__ uint32_t g_a1lo[(size_t)MAX_NODES * KW];
__device__ uint32_t g_w1hi[D_HID * KW], g_w1lo[D_HID * KW];
__device__ uint32_t g_w2hi[D_CLS * KW], g_w2lo[D_CLS * KW];
__device__ float    g_dinv[MAX_NODES];
__device__ int      g_cnt [MAX_NODES];
__device__ int      g_off [MAX_NODES];
__device__ int      g_cur [MAX_NODES];
__device__ int      g_srcsort[MAX_EDGES];
__device__ int      g_bsum[1024];
__device__ int      g_boff[1024];

// ---------------- helpers ----------------
__device__ __forceinline__ void split2_bf16(float2 v, uint32_t& hi, uint32_t& lo) {
    __nv_bfloat16 hx = __float2bfloat16(v.x);
    __nv_bfloat16 hy = __float2bfloat16(v.y);
    __nv_bfloat16 lx = __float2bfloat16(v.x - __bfloat162float(hx));
    __nv_bfloat16 ly = __float2bfloat16(v.y - __bfloat162float(hy));
    hi = (uint32_t)__bfloat16_as_ushort(hx) | ((uint32_t)__bfloat16_as_ushort(hy) << 16);
    lo = (uint32_t)__bfloat16_as_ushort(lx) | ((uint32_t)__bfloat16_as_ushort(ly) << 16);
}

__device__ __forceinline__ void cp_async16(uint32_t dst, const void* src, bool pred) {
    int sz = pred ? 16 : 0;
    asm volatile("cp.async.cg.shared.global [%0], [%1], 16, %2;"
                 :: "r"(dst), "l"(src), "r"(sz) : "memory");
}

__device__ __forceinline__ void ldsm_x4(uint32_t r[4], uint32_t addr) {
    asm volatile("ldmatrix.sync.aligned.m8n8.x4.shared.b16 {%0,%1,%2,%3}, [%4];"
                 : "=r"(r[0]), "=r"(r[1]), "=r"(r[2]), "=r"(r[3]) : "r"(addr));
}

__device__ __forceinline__ void mma_bf16(float c[4], const uint32_t a[4],
                                         uint32_t b0, uint32_t b1) {
    asm volatile(
        "mma.sync.aligned.m16n8k16.row.col.f32.bf16.bf16.f32 "
        "{%0,%1,%2,%3}, {%4,%5,%6,%7}, {%8,%9}, {%0,%1,%2,%3};"
        : "+f"(c[0]), "+f"(c[1]), "+f"(c[2]), "+f"(c[3])
        : "r"(a[0]), "r"(a[1]), "r"(a[2]), "r"(a[3]), "r"(b0), "r"(b1));
}

// ---------------- pre-split kernels ----------------
__global__ void split_x(const float* __restrict__ x, uint32_t* __restrict__ xhi,
                        uint32_t* __restrict__ xlo, int* __restrict__ cnt,
                        int n, long nw) {
    long i0 = (long)blockIdx.x * blockDim.x + threadIdx.x;
    if (i0 < n) cnt[i0] = 0;
    long stride = (long)gridDim.x * blockDim.x;
    for (long i = i0; i < nw; i += stride) {
        float2 v = ((const float2*)x)[i];
        uint32_t hi, lo;
        split2_bf16(v, hi, lo);
        xhi[i] = hi;
        xlo[i] = lo;
    }
}

__global__ void split_w(const float* __restrict__ W1, const float* __restrict__ W2,
                        uint32_t* w1hi, uint32_t* w1lo,
                        uint32_t* w2hi, uint32_t* w2lo) {
    int i = blockIdx.x * 256 + threadIdx.x;
    if (i < D_HID * KW) {
        int nn = i >> 7, w = i & (KW - 1);
        float2 v = make_float2(W1[(2 * w) * D_HID + nn], W1[(2 * w + 1) * D_HID + nn]);
        uint32_t hi, lo;
        split2_bf16(v, hi, lo);
        w1hi[i] = hi; w1lo[i] = lo;
    } else if (i < D_HID * KW + D_CLS * KW) {
        int j = i - D_HID * KW;
        int nn = j >> 7, w = j & (KW - 1);
        float2 v = make_float2(W2[(2 * w) * D_CLS + nn], W2[(2 * w + 1) * D_CLS + nn]);
        uint32_t hi, lo;
        split2_bf16(v, hi, lo);
        w2hi[j] = hi; w2lo[j] = lo;
    }
}

// ---------------- CSR build ----------------
__global__ void count_dst(const int* __restrict__ dst, int* cnt, int E) {
    int e = blockIdx.x * blockDim.x + threadIdx.x;
    if (e < E) atomicAdd(&cnt[dst[e]], 1);
}

__global__ void dinv_k(const int* __restrict__ cnt, float* dinv, int n) {
    int i = blockIdx.x * blockDim.x + threadIdx.x;
    if (i < n) dinv[i] = rsqrtf((float)(cnt[i] + 1));
}

__global__ void block_sums(const int* __restrict__ cnt, int* bsum, int n) {
    __shared__ int sh[256];
    int i = blockIdx.x * 256 + threadIdx.x;
    sh[threadIdx.x] = (i < n) ? cnt[i] : 0;
    __syncthreads();
    for (int o = 128; o > 0; o >>= 1) {
        if (threadIdx.x < o) sh[threadIdx.x] += sh[threadIdx.x + o];
        __syncthreads();
    }
    if (threadIdx.x == 0) bsum[blockIdx.x] = sh[0];
}

__global__ void scan_bsums(const int* __restrict__ bsum, int* boff, int nb) {
    __shared__ int sh[1024];
    int t = threadIdx.x;
    int v = (t < nb) ? bsum[t] : 0;
    sh[t] = v;
    __syncthreads();
    for (int o = 1; o < 1024; o <<= 1) {
        int u = (t >= o) ? sh[t - o] : 0;
        __syncthreads();
        sh[t] += u;
        __syncthreads();
    }
    if (t < nb) boff[t] = sh[t] - v;
}

__global__ void scan_final(const int* __restrict__ cnt, const int* __restrict__ boff,
                           int* off, int* cur, int n) {
    __shared__ int sh[256];
    int i = blockIdx.x * 256 + threadIdx.x;
    int v = (i < n) ? cnt[i] : 0;
    sh[threadIdx.x] = v;
    __syncthreads();
    for (int o = 1; o < 256; o <<= 1) {
        int u = (threadIdx.x >= o) ? sh[threadIdx.x - o] : 0;
        __syncthreads();
        sh[threadIdx.x] += u;
        __syncthreads();
    }
    if (i < n) {
        int excl = boff[blockIdx.x] + sh[threadIdx.x] - v;
        off[i] = excl;
        cur[i] = excl;
    }
}

__global__ void place_edges(const int* __restrict__ src, const int* __restrict__ dst,
                            int* cur, int* srcsort, int E) {
    int e = blockIdx.x * blockDim.x + threadIdx.x;
    if (e < E) {
        int d = dst[e];
        int pos = atomicAdd(&cur[d], 1);
        srcsort[pos] = src[e];
    }
}

// ====== 3xBF16 GEMM: BK=32, 3-stage cp.async, ONE barrier per k-iteration ======
// Stage layout: [A_hi(ASZ) | A_lo(ASZ) | B_hi(BSZ) | B_lo(BSZ)], STR=20 words/row.
__global__ __launch_bounds__(256)
void gemm_bf16x3(const uint32_t* __restrict__ Ahi, const uint32_t* __restrict__ Alo,
                 const uint32_t* __restrict__ Bhi, const uint32_t* __restrict__ Blo,
                 float* __restrict__ C, int M, int N) {
    constexpr int BM = 128, BN = 64, STR = 20;       // 16 data words + 4 pad
    constexpr int MT = 2, NT = 4;
    constexpr int ASZ = BM * STR, BSZ = BN * STR;    // words
    constexpr int TILES = KDIM / 32;                 // 8
    constexpr int STAGES = 3;
    constexpr uint32_t STAGE_B = (uint32_t)(2 * ASZ + 2 * BSZ) * 4;  // 30720 bytes

    extern __shared__ __align__(16) uint32_t smem_dyn[];

    const int tid  = threadIdx.x;
    const int wid  = tid >> 5;
    const int lane = tid & 31;
    const int g    = lane >> 2;
    const int tig  = lane & 3;
    const int q    = lane >> 3;
    const int lr   = lane & 7;
    const int row0 = blockIdx.y * BM;
    const int col0 = blockIdx.x * BN;
    const int warpM = (wid >> 1) * 32;
    const int warpN = (wid & 1) * 32;

    const uint32_t base = (uint32_t)__cvta_generic_to_shared(smem_dyn);
    const uint32_t a_hi_b = base;
    const uint32_t a_lo_b = base + (uint32_t)ASZ * 4;
    const uint32_t b_hi_b = base + (uint32_t)(2 * ASZ) * 4;
    const uint32_t b_lo_b = base + (uint32_t)(2 * ASZ + BSZ) * 4;

    // cp.async mapping: A = 128 rows x 4 16B-quarters = 512 chunks, 2 per thread
    uint32_t a_dst[2]; size_t a_srcb[2]; bool a_ok[2];
#pragma unroll
    for (int j = 0; j < 2; j++) {
        int c = tid + j * 256;
        int ar = c >> 2, aq = c & 3;
        a_dst[j]  = (uint32_t)((ar * STR + aq * 4) * 4);
        a_srcb[j] = (size_t)(row0 + ar) * KW + aq * 4;
        a_ok[j]   = (row0 + ar) < M;
    }
    // B = 64 rows x 4 quarters = 256 chunks, 1 per thread (both hi and lo)
    const int br = tid >> 2, bq = tid & 3;
    const uint32_t b_dst = (uint32_t)((br * STR + bq * 4) * 4);
    const size_t   b_srcb = (size_t)(col0 + br) * KW + bq * 4;

    // ldmatrix per-lane byte offsets within a stage (per k16-half add h*32B)
    uint32_t a_off[MT], b_off[2];
#pragma unroll
    for (int mt = 0; mt < MT; mt++)
        a_off[mt] = (uint32_t)(((warpM + mt * 16 + (q & 1) * 8 + lr) * STR + (q >> 1) * 4) * 4);
#pragma unroll
    for (int p = 0; p < 2; p++)
        b_off[p] = (uint32_t)(((warpN + (2 * p + (q >> 1)) * 8 + lr) * STR + (q & 1) * 4) * 4);

    float acc[MT][NT][4];
#pragma unroll
    for (int mt = 0; mt < MT; mt++)
#pragma unroll
        for (int nt = 0; nt < NT; nt++)
#pragma unroll
            for (int i = 0; i < 4; i++) acc[mt][nt][i] = 0.0f;

#define ISSUE_TILE(T)                                                              \
    do {                                                                           \
        uint32_t so = (uint32_t)((T) % STAGES) * STAGE_B;                          \
        int kw_ = (T) * 16;                                                        \
        cp_async16(a_hi_b + so + a_dst[0], Ahi + a_srcb[0] + kw_, a_ok[0]);        \
        cp_async16(a_hi_b + so + a_dst[1], Ahi + a_srcb[1] + kw_, a_ok[1]);        \
        cp_async16(a_lo_b + so + a_dst[0], Alo + a_srcb[0] + kw_, a_ok[0]);        \
        cp_async16(a_lo_b + so + a_dst[1], Alo + a_srcb[1] + kw_, a_ok[1]);        \
        cp_async16(b_hi_b + so + b_dst, Bhi + b_srcb + kw_, true);                 \
        cp_async16(b_lo_b + so + b_dst, Blo + b_srcb + kw_, true);                 \
    } while (0)

    // prologue: tiles 0,1 in flight (one group each)
    ISSUE_TILE(0);
    asm volatile("cp.async.commit_group;" ::: "memory");
    ISSUE_TILE(1);
    asm volatile("cp.async.commit_group;" ::: "memory");

#pragma unroll 1
    for (int t = 0; t < TILES; t++) {
        // tile t resident when <=1 group outstanding (newest = tile t+1)
        asm volatile("cp.async.wait_group 1;" ::: "memory");
        __syncthreads();   // also: all warps done READING stage (t-1)%3 == (t+2)%3

        if (t + 2 < TILES) {
            ISSUE_TILE(t + 2);
            asm volatile("cp.async.commit_group;" ::: "memory");
        }

        const uint32_t so = (uint32_t)(t % STAGES) * STAGE_B;
#pragma unroll
        for (int h = 0; h < 2; h++) {       // two k16 sub-steps
            const uint32_t ho = so + (uint32_t)h * 32;
            uint32_t a_hi[MT][4], a_lo[MT][4];
#pragma unroll
            for (int mt = 0; mt < MT; mt++) {
                ldsm_x4(a_hi[mt], a_hi_b + ho + a_off[mt]);
                ldsm_x4(a_lo[mt], a_lo_b + ho + a_off[mt]);
            }
            uint32_t b_hi[2][4], b_lo[2][4];
#pragma unroll
            for (int p = 0; p < 2; p++) {
                ldsm_x4(b_hi[p], b_hi_b + ho + b_off[p]);
                ldsm_x4(b_lo[p], b_lo_b + ho + b_off[p]);
            }
#pragma unroll
            for (int mt = 0; mt < MT; mt++)
#pragma unroll
                for (int nt = 0; nt < NT; nt++) {
                    int p = nt >> 1, o = (nt & 1) * 2;
                    mma_bf16(acc[mt][nt], a_hi[mt], b_lo[p][o], b_lo[p][o + 1]);
                    mma_bf16(acc[mt][nt], a_lo[mt], b_hi[p][o], b_hi[p][o + 1]);
                    mma_bf16(acc[mt][nt], a_hi[mt], b_hi[p][o], b_hi[p][o + 1]);
                }
        }
    }
#undef ISSUE_TILE

#pragma unroll
    for (int mt = 0; mt < MT; mt++) {
        int r1 = row0 + warpM + mt * 16 + g;
        int r2 = r1 + 8;
#pragma unroll
        for (int nt = 0; nt < NT; nt++) {
            int cc = col0 + warpN + nt * 8 + 2 * tig;
            if (r1 < M)
                *(float2*)(C + (size_t)r1 * N + cc) = make_float2(acc[mt][nt][0], acc[mt][nt][1]);
            if (r2 < M)
                *(float2*)(C + (size_t)r2 * N + cc) = make_float2(acc[mt][nt][2], acc[mt][nt][3]);
        }
    }
}

// ====== layer-1 aggregate ======
__global__ void agg1_kernel(const float* __restrict__ h,
                            const int* __restrict__ srcsort,
                            const int* __restrict__ off,
                            const float* __restrict__ dinv,
                            const float* __restrict__ b1,
                            uint32_t* __restrict__ a1hi, uint32_t* __restrict__ a1lo,
                            int n, int E) {
    int node = blockIdx.x * (blockDim.x >> 5) + (threadIdx.x >> 5);
    if (node >= n) return;
    int lane = threadIdx.x & 31;

    float di = dinv[node];
    const float4* hp = (const float4*)(h + (size_t)node * D_HID);
    float4 v0 = __ldg(hp + lane);
    float4 v1 = __ldg(hp + lane + 32);
    float4 a0 = make_float4(v0.x * di, v0.y * di, v0.z * di, v0.w * di);
    float4 a1 = make_float4(v1.x * di, v1.y * di, v1.z * di, v1.w * di);

    int e0 = off[node];
    int e1 = (node + 1 < n) ? off[node + 1] : E;
    for (int e = e0; e < e1; e++) {
        int s = srcsort[e];
        float ds = __ldg(dinv + s);
        const float4* sp = (const float4*)(h + (size_t)s * D_HID);
        float4 u0 = __ldg(sp + lane);
        float4 u1 = __ldg(sp + lane + 32);
        a0.x = fmaf(u0.x, ds, a0.x); a0.y = fmaf(u0.y, ds, a0.y);
        a0.z = fmaf(u0.z, ds, a0.z); a0.w = fmaf(u0.w, ds, a0.w);
        a1.x = fmaf(u1.x, ds, a1.x); a1.y = fmaf(u1.y, ds, a1.y);
        a1.z = fmaf(u1.z, ds, a1.z); a1.w = fmaf(u1.w, ds, a1.w);
    }

    const float4* bb = (const float4*)b1;
    float4 c0 = __ldg(bb + lane);
    float4 c1 = __ldg(bb + lane + 32);
    float4 r0, r1;
    r0.x = fmaxf(fmaf(a0.x, di, c0.x), 0.0f);
    r0.y = fmaxf(fmaf(a0.y, di, c0.y), 0.0f);
    r0.z = fmaxf(fmaf(a0.z, di, c0.z), 0.0f);
    r0.w = fmaxf(fmaf(a0.w, di, c0.w), 0.0f);
    r1.x = fmaxf(fmaf(a1.x, di, c1.x), 0.0f);
    r1.y = fmaxf(fmaf(a1.y, di, c1.y), 0.0f);
    r1.z = fmaxf(fmaf(a1.z, di, c1.z), 0.0f);
    r1.w = fmaxf(fmaf(a1.w, di, c1.w), 0.0f);

    uint32_t h0a, l0a, h0b, l0b, h1a, l1a, h1b, l1b;
    split2_bf16(make_float2(r0.x, r0.y), h0a, l0a);
    split2_bf16(make_float2(r0.z, r0.w), h0b, l0b);
    split2_bf16(make_float2(r1.x, r1.y), h1a, l1a);
    split2_bf16(make_float2(r1.z, r1.w), h1b, l1b);
    uint2* ophi = (uint2*)(a1hi + (size_t)node * KW);
    uint2* oplo = (uint2*)(a1lo + (size_t)node * KW);
    ophi[lane]      = make_uint2(h0a, h0b);
    ophi[lane + 32] = make_uint2(h1a, h1b);
    oplo[lane]      = make_uint2(l0a, l0b);
    oplo[lane + 32] = make_uint2(l1a, l1b);
}

// ====== layer-2 aggregate ======
__global__ void agg2_kernel(const float* __restrict__ h,
                            const int* __restrict__ srcsort,
                            const int* __restrict__ off,
                            const float* __restrict__ dinv,
                            const float* __restrict__ b2,
                            float* __restrict__ out, int n, int E) {
    int node = blockIdx.x * (blockDim.x >> 5) + (threadIdx.x >> 5);
    if (node >= n) return;
    int lane = threadIdx.x & 31;

    float di = dinv[node];
    const float2* hp = (const float2*)(h + (size_t)node * D_CLS);
    float2 u = __ldg(hp + lane);
    float2 a = make_float2(u.x * di, u.y * di);

    int e0 = off[node];
    int e1 = (node + 1 < n) ? off[node + 1] : E;
    for (int e = e0; e < e1; e++) {
        int s = srcsort[e];
        float ds = __ldg(dinv + s);
        float2 v = __ldg(((const float2*)(h + (size_t)s * D_CLS)) + lane);
        a.x = fmaf(v.x, ds, a.x);
        a.y = fmaf(v.y, ds, a.y);
    }

    float v0 = fmaf(a.x, di, __ldg(b2 + 2 * lane));
    float v1 = fmaf(a.y, di, __ldg(b2 + 2 * lane + 1));

    float m = fmaxf(v0, v1);
#pragma unroll
    for (int o = 16; o > 0; o >>= 1) m = fmaxf(m, __shfl_xor_sync(0xFFFFFFFFu, m, o));
    float s = __expf(v0 - m) + __expf(v1 - m);
#pragma unroll
    for (int o = 16; o > 0; o >>= 1) s += __shfl_xor_sync(0xFFFFFFFFu, s, o);
    float lse = m + __logf(s);

    float2* op = (float2*)(out + (size_t)node * D_CLS);
    op[lane] = make_float2(v0 - lse, v1 - lse);
}

extern "C" void kernel_launch(void* const* d_in, const int* in_sizes, int n_in,
                              void* d_out, int out_size) {
    const float* x   = (const float*)d_in[0];
    const int*   ei  = (const int*)d_in[1];   // JAX int64 request silently -> int32
    const float* W1  = (const float*)d_in[2];
    const float* b1  = (const float*)d_in[3];
    const float* W2  = (const float*)d_in[4];
    const float* b2  = (const float*)d_in[5];
    float*       out = (float*)d_out;

    const int n = in_sizes[0] / D_IN;
    const int E = in_sizes[1] / 2;
    const int* src = ei;
    const int* dst = ei + E;

    float *h1, *h2, *dinv;
    uint32_t *xhi, *xlo, *a1hi, *a1lo, *w1hi, *w1lo, *w2hi, *w2lo;
    int *cnt, *off, *cur, *srcsort, *bsum, *boff;
    cudaGetSymbolAddress((void**)&h1,   g_h1);
    cudaGetSymbolAddress((void**)&h2,   g_h2);
    cudaGetSymbolAddress((void**)&xhi,  g_xhi);
    cudaGetSymbolAddress((void**)&xlo,  g_xlo);
    cudaGetSymbolAddress((void**)&a1hi, g_a1hi);
    cudaGetSymbolAddress((void**)&a1lo, g_a1lo);
    cudaGetSymbolAddress((void**)&w1hi, g_w1hi);
    cudaGetSymbolAddress((void**)&w1lo, g_w1lo);
    cudaGetSymbolAddress((void**)&w2hi, g_w2hi);
    cudaGetSymbolAddress((void**)&w2lo, g_w2lo);
    cudaGetSymbolAddress((void**)&dinv, g_dinv);
    cudaGetSymbolAddress((void**)&cnt,  g_cnt);
    cudaGetSymbolAddress((void**)&off,  g_off);
    cudaGetSymbolAddress((void**)&cur,  g_cur);
    cudaGetSymbolAddress((void**)&srcsort, g_srcsort);
    cudaGetSymbolAddress((void**)&bsum, g_bsum);
    cudaGetSymbolAddress((void**)&boff, g_boff);

    const int NB = (n + 255) / 256;   // <= 1024
    const int MB = (n + 127) / 128;
    const long nwords = (long)n * KW;

    // 3-stage BK=32 pipeline: 90KB dynamic smem
    const int SMEM_GEMM = 3 * (2 * 128 * 20 + 2 * 64 * 20) * 4;   // 92160
    cudaFuncSetAttribute(gemm_bf16x3, cudaFuncAttributeMaxDynamicSharedMemorySize, SMEM_GEMM);

    // 1: split x (+ zero cnt), 2: split weights, 3: degree count
    split_x<<<2048, 256>>>(x, xhi, xlo, cnt, n, nwords);
    split_w<<<(D_HID * KW + D_CLS * KW + 255) / 256, 256>>>(W1, W2, w1hi, w1lo, w2hi, w2lo);
    count_dst<<<(E + 255) / 256, 256>>>(dst, cnt, E);

    // 4: GEMM1 (profiler capture slot): h1 = x @ W1
    gemm_bf16x3<<<dim3(D_HID / 64, MB), 256, SMEM_GEMM>>>(xhi, xlo, w1hi, w1lo, h1, n, D_HID);

    // dinv + CSR
    dinv_k     <<<NB, 256>>>(cnt, dinv, n);
    block_sums <<<NB, 256>>>(cnt, bsum, n);
    scan_bsums <<<1, 1024>>>(bsum, boff, NB);
    scan_final <<<NB, 256>>>(cnt, boff, off, cur, n);
    place_edges<<<(E + 255) / 256, 256>>>(src, dst, cur, srcsort, E);

    // agg1: normalize+aggregate+bias+relu, emit split bf16
    agg1_kernel<<<(n + 7) / 8, 256>>>(h1, srcsort, off, dinv, b1, a1hi, a1lo, n, E);

    // GEMM2: h2 = agg1 @ W2
    gemm_bf16x3<<<dim3(D_CLS / 64, MB), 256, SMEM_GEMM>>>(a1hi, a1lo, w2hi, w2lo, h2, n, D_CLS);

    // agg2: normalize+aggregate+bias+log_softmax
    agg2_kernel<<<(n + 7) / 8, 256>>>(h2, srcsort, off, dinv, b2, out, n, E);
}

// round 14
// speedup vs baseline: 1.2019x; 1.1100x over previous
#include <cuda_runtime.h>
#include <cuda_bf16.h>
#include <math.h>
#include <stdint.h>

// ---------------- problem constants ----------------
#define MAX_NODES 100000
#define MAX_EDGES 2000000
#define D_IN  256
#define D_HID 256
#define D_CLS 64
#define KDIM  256
#define KW    (KDIM / 2)   // packed bf16x2 words per row

// ---------------- scratch (static, no allocs) ----------------
__device__ float    g_h1  [(size_t)MAX_NODES * D_HID];
__device__ float    g_h2  [(size_t)MAX_NODES * D_CLS];
__device__ uint32_t g_xhi [(size_t)MAX_NODES * KW];
__device__ uint32_t g_xlo [(size_t)MAX_NODES * KW];
__device__ uint32_t g_a1hi[(size_t)MAX_NODES * KW];
__device__ uint32_t g_a1lo[(size_t)MAX_NODES * KW];
__device__ uint32_t g_w1hi[D_HID * KW], g_w1lo[D_HID * KW];
__device__ uint32_t g_w2hi[D_CLS * KW], g_w2lo[D_CLS * KW];
__device__ float    g_dinv[MAX_NODES];
__device__ int      g_cnt [MAX_NODES];
__device__ int      g_off [MAX_NODES];
__device__ int      g_cur [MAX_NODES];
__device__ int      g_srcsort[MAX_EDGES];
__device__ int      g_bsum[1024];
__device__ int      g_boff[1024];

// ---------------- helpers ----------------
__device__ __forceinline__ void split2_bf16(float2 v, uint32_t& hi, uint32_t& lo) {
    __nv_bfloat16 hx = __float2bfloat16(v.x);
    __nv_bfloat16 hy = __float2bfloat16(v.y);
    __nv_bfloat16 lx = __float2bfloat16(v.x - __bfloat162float(hx));
    __nv_bfloat16 ly = __float2bfloat16(v.y - __bfloat162float(hy));
    hi = (uint32_t)__bfloat16_as_ushort(hx) | ((uint32_t)__bfloat16_as_ushort(hy) << 16);
    lo = (uint32_t)__bfloat16_as_ushort(lx) | ((uint32_t)__bfloat16_as_ushort(ly) << 16);
}

__device__ __forceinline__ void cp_async16(uint32_t dst, const void* src, bool pred) {
    int sz = pred ? 16 : 0;
    asm volatile("cp.async.cg.shared.global [%0], [%1], 16, %2;"
                 :: "r"(dst), "l"(src), "r"(sz) : "memory");
}

__device__ __forceinline__ void ldsm_x4(uint32_t r[4], uint32_t addr) {
    asm volatile("ldmatrix.sync.aligned.m8n8.x4.shared.b16 {%0,%1,%2,%3}, [%4];"
                 : "=r"(r[0]), "=r"(r[1]), "=r"(r[2]), "=r"(r[3]) : "r"(addr));
}

__device__ __forceinline__ void mma_bf16(float c[4], const uint32_t a[4],
                                         uint32_t b0, uint32_t b1) {
    asm volatile(
        "mma.sync.aligned.m16n8k16.row.col.f32.bf16.bf16.f32 "
        "{%0,%1,%2,%3}, {%4,%5,%6,%7}, {%8,%9}, {%0,%1,%2,%3};"
        : "+f"(c[0]), "+f"(c[1]), "+f"(c[2]), "+f"(c[3])
        : "r"(a[0]), "r"(a[1]), "r"(a[2]), "r"(a[3]), "r"(b0), "r"(b1));
}

// swizzled byte offset within a matrix region: 64B rows of 4x16B chunks,
// chunk column permuted by row so ldmatrix phases hit 8 distinct bank-groups.
__device__ __forceinline__ uint32_t swz(int row, int q) {
    return (uint32_t)(row * 64 + ((q ^ ((row >> 1) & 3)) * 16));
}

// ---------------- pre-split kernels ----------------
__global__ void split_x(const float* __restrict__ x, uint32_t* __restrict__ xhi,
                        uint32_t* __restrict__ xlo, int* __restrict__ cnt,
                        int n, long nw) {
    long i0 = (long)blockIdx.x * blockDim.x + threadIdx.x;
    if (i0 < n) cnt[i0] = 0;
    long stride = (long)gridDim.x * blockDim.x;
    for (long i = i0; i < nw; i += stride) {
        float2 v = ((const float2*)x)[i];
        uint32_t hi, lo;
        split2_bf16(v, hi, lo);
        xhi[i] = hi;
        xlo[i] = lo;
    }
}

__global__ void split_w(const float* __restrict__ W1, const float* __restrict__ W2,
                        uint32_t* w1hi, uint32_t* w1lo,
                        uint32_t* w2hi, uint32_t* w2lo) {
    int i = blockIdx.x * 256 + threadIdx.x;
    if (i < D_HID * KW) {
        int nn = i >> 7, w = i & (KW - 1);
        float2 v = make_float2(W1[(2 * w) * D_HID + nn], W1[(2 * w + 1) * D_HID + nn]);
        uint32_t hi, lo;
        split2_bf16(v, hi, lo);
        w1hi[i] = hi; w1lo[i] = lo;
    } else if (i < D_HID * KW + D_CLS * KW) {
        int j = i - D_HID * KW;
        int nn = j >> 7, w = j & (KW - 1);
        float2 v = make_float2(W2[(2 * w) * D_CLS + nn], W2[(2 * w + 1) * D_CLS + nn]);
        uint32_t hi, lo;
        split2_bf16(v, hi, lo);
        w2hi[j] = hi; w2lo[j] = lo;
    }
}

// ---------------- CSR build ----------------
__global__ void count_dst(const int* __restrict__ dst, int* cnt, int E) {
    int e = blockIdx.x * blockDim.x + threadIdx.x;
    if (e < E) atomicAdd(&cnt[dst[e]], 1);
}

__global__ void block_sums(const int* __restrict__ cnt, int* bsum, int n) {
    __shared__ int sh[256];
    int i = blockIdx.x * 256 + threadIdx.x;
    sh[threadIdx.x] = (i < n) ? cnt[i] : 0;
    __syncthreads();
    for (int o = 128; o > 0; o >>= 1) {
        if (threadIdx.x < o) sh[threadIdx.x] += sh[threadIdx.x + o];
        __syncthreads();
    }
    if (threadIdx.x == 0) bsum[blockIdx.x] = sh[0];
}

__global__ void scan_bsums(const int* __restrict__ bsum, int* boff, int nb) {
    __shared__ int sh[1024];
    int t = threadIdx.x;
    int v = (t < nb) ? bsum[t] : 0;
    sh[t] = v;
    __syncthreads();
    for (int o = 1; o < 1024; o <<= 1) {
        int u = (t >= o) ? sh[t - o] : 0;
        __syncthreads();
        sh[t] += u;
        __syncthreads();
    }
    if (t < nb) boff[t] = sh[t] - v;
}

__global__ void scan_final(const int* __restrict__ cnt, const int* __restrict__ boff,
                           int* off, int* cur, float* dinv, int n) {
    __shared__ int sh[256];
    int i = blockIdx.x * 256 + threadIdx.x;
    int v = (i < n) ? cnt[i] : 0;
    sh[threadIdx.x] = v;
    __syncthreads();
    for (int o = 1; o < 256; o <<= 1) {
        int u = (threadIdx.x >= o) ? sh[threadIdx.x - o] : 0;
        __syncthreads();
        sh[threadIdx.x] += u;
        __syncthreads();
    }
    if (i < n) {
        int excl = boff[blockIdx.x] + sh[threadIdx.x] - v;
        off[i] = excl;
        cur[i] = excl;
        dinv[i] = rsqrtf((float)(v + 1));  // +1 self loop
    }
}

__global__ void place_edges(const int* __restrict__ src, const int* __restrict__ dst,
                            int* cur, int* srcsort, int E) {
    int e = blockIdx.x * blockDim.x + threadIdx.x;
    if (e < E) {
        int d = dst[e];
        int pos = atomicAdd(&cur[d], 1);
        srcsort[pos] = src[e];
    }
}

// ====== 3xBF16 GEMM: BK=32, 3-stage cp.async, swizzled smem (no padding) ======
// Stage layout: [A_hi 8K | A_lo 8K | B_hi 4K | B_lo 4K] = 24576 bytes.
// Rows are 64B (16 words = k32); 16B chunks permuted by swz() for conflict-free LDSM.
__global__ __launch_bounds__(256, 3)
void gemm_bf16x3(const uint32_t* __restrict__ Ahi, const uint32_t* __restrict__ Alo,
                 const uint32_t* __restrict__ Bhi, const uint32_t* __restrict__ Blo,
                 float* __restrict__ C, int M, int N) {
    constexpr int MT = 2, NT = 4;
    constexpr int TILES = KDIM / 32;                 // 8
    constexpr int STAGES = 3;
    constexpr uint32_t A_BYTES = 128 * 64;           // 8192 per array
    constexpr uint32_t B_BYTES = 64 * 64;            // 4096 per array
    constexpr uint32_t STAGE_B = 2 * A_BYTES + 2 * B_BYTES;  // 24576

    extern __shared__ __align__(16) uint32_t smem_dyn[];

    const int tid  = threadIdx.x;
    const int wid  = tid >> 5;
    const int lane = tid & 31;
    const int g    = lane >> 2;
    const int tig  = lane & 3;
    const int q    = lane >> 3;       // ldmatrix group 0..3
    const int lr   = lane & 7;
    const int row0 = blockIdx.y * 128;
    const int col0 = blockIdx.x * 64;
    const int warpM = (wid >> 1) * 32;
    const int warpN = (wid & 1) * 32;

    const uint32_t base = (uint32_t)__cvta_generic_to_shared(smem_dyn);
    const uint32_t a_hi_b = base;
    const uint32_t a_lo_b = base + A_BYTES;
    const uint32_t b_hi_b = base + 2 * A_BYTES;
    const uint32_t b_lo_b = base + 2 * A_BYTES + B_BYTES;

    // cp.async mapping: A = 128 rows x 4 chunks = 512; 2 per thread (hi and lo each)
    uint32_t a_dst[2]; size_t a_srcb[2]; bool a_ok[2];
#pragma unroll
    for (int j = 0; j < 2; j++) {
        int c = tid + j * 256;
        int ar = c >> 2, aq = c & 3;
        a_dst[j]  = swz(ar, aq);
        a_srcb[j] = (size_t)(row0 + ar) * KW + aq * 4;
        a_ok[j]   = (row0 + ar) < M;
    }
    // B = 64 rows x 4 chunks = 256; 1 per thread (hi and lo each)
    const int br = tid >> 2, bq = tid & 3;
    const uint32_t b_dst = swz(br, bq);
    const size_t   b_srcb = (size_t)(col0 + br) * KW + bq * 4;

    // ldmatrix per-lane byte offsets, per k16-half h
    uint32_t a_off[MT][2], b_off[2][2];
#pragma unroll
    for (int mt = 0; mt < MT; mt++) {
        int row = warpM + mt * 16 + (q & 1) * 8 + lr;
#pragma unroll
        for (int h = 0; h < 2; h++)
            a_off[mt][h] = swz(row, h * 2 + (q >> 1));
    }
#pragma unroll
    for (int p = 0; p < 2; p++) {
        int row = warpN + (2 * p + (q >> 1)) * 8 + lr;
#pragma unroll
        for (int h = 0; h < 2; h++)
            b_off[p][h] = swz(row, h * 2 + (q & 1));
    }

    float acc[MT][NT][4];
#pragma unroll
    for (int mt = 0; mt < MT; mt++)
#pragma unroll
        for (int nt = 0; nt < NT; nt++)
#pragma unroll
            for (int i = 0; i < 4; i++) acc[mt][nt][i] = 0.0f;

#define ISSUE_TILE(T)                                                              \
    do {                                                                           \
        uint32_t so = (uint32_t)((T) % STAGES) * STAGE_B;                          \
        int kw_ = (T) * 16;                                                        \
        cp_async16(a_hi_b + so + a_dst[0], Ahi + a_srcb[0] + kw_, a_ok[0]);        \
        cp_async16(a_hi_b + so + a_dst[1], Ahi + a_srcb[1] + kw_, a_ok[1]);        \
        cp_async16(a_lo_b + so + a_dst[0], Alo + a_srcb[0] + kw_, a_ok[0]);        \
        cp_async16(a_lo_b + so + a_dst[1], Alo + a_srcb[1] + kw_, a_ok[1]);        \
        cp_async16(b_hi_b + so + b_dst, Bhi + b_srcb + kw_, true);                 \
        cp_async16(b_lo_b + so + b_dst, Blo + b_srcb + kw_, true);                 \
    } while (0)

    // prologue: tiles 0,1 in flight
    ISSUE_TILE(0);
    asm volatile("cp.async.commit_group;" ::: "memory");
    ISSUE_TILE(1);
    asm volatile("cp.async.commit_group;" ::: "memory");

#pragma unroll 1
    for (int t = 0; t < TILES; t++) {
        asm volatile("cp.async.wait_group 1;" ::: "memory");
        __syncthreads();   // tile t resident; stage (t+2)%3 free of readers

        if (t + 2 < TILES) {
            ISSUE_TILE(t + 2);
            asm volatile("cp.async.commit_group;" ::: "memory");
        }

        const uint32_t so = (uint32_t)(t % STAGES) * STAGE_B;
#pragma unroll
        for (int h = 0; h < 2; h++) {       // two k16 sub-steps
            uint32_t a_hi[MT][4], a_lo[MT][4];
#pragma unroll
            for (int mt = 0; mt < MT; mt++) {
                ldsm_x4(a_hi[mt], a_hi_b + so + a_off[mt][h]);
                ldsm_x4(a_lo[mt], a_lo_b + so + a_off[mt][h]);
            }
            uint32_t b_hi[2][4], b_lo[2][4];
#pragma unroll
            for (int p = 0; p < 2; p++) {
                ldsm_x4(b_hi[p], b_hi_b + so + b_off[p][h]);
                ldsm_x4(b_lo[p], b_lo_b + so + b_off[p][h]);
            }
#pragma unroll
            for (int mt = 0; mt < MT; mt++)
#pragma unroll
                for (int nt = 0; nt < NT; nt++) {
                    int p = nt >> 1, o = (nt & 1) * 2;
                    mma_bf16(acc[mt][nt], a_hi[mt], b_lo[p][o], b_lo[p][o + 1]);
                    mma_bf16(acc[mt][nt], a_lo[mt], b_hi[p][o], b_hi[p][o + 1]);
                    mma_bf16(acc[mt][nt], a_hi[mt], b_hi[p][o], b_hi[p][o + 1]);
                }
        }
    }
#undef ISSUE_TILE

#pragma unroll
    for (int mt = 0; mt < MT; mt++) {
        int r1 = row0 + warpM + mt * 16 + g;
        int r2 = r1 + 8;
#pragma unroll
        for (int nt = 0; nt < NT; nt++) {
            int cc = col0 + warpN + nt * 8 + 2 * tig;
            if (r1 < M)
                *(float2*)(C + (size_t)r1 * N + cc) = make_float2(acc[mt][nt][0], acc[mt][nt][1]);
            if (r2 < M)
                *(float2*)(C + (size_t)r2 * N + cc) = make_float2(acc[mt][nt][2], acc[mt][nt][3]);
        }
    }
}

// ====== layer-1 aggregate ======
__global__ void agg1_kernel(const float* __restrict__ h,
                            const int* __restrict__ srcsort,
                            const int* __restrict__ off,
                            const float* __restrict__ dinv,
                            const float* __restrict__ b1,
                            uint32_t* __restrict__ a1hi, uint32_t* __restrict__ a1lo,
                            int n, int E) {
    int node = blockIdx.x * (blockDim.x >> 5) + (threadIdx.x >> 5);
    if (node >= n) return;
    int lane = threadIdx.x & 31;

    float di = dinv[node];
    const float4* hp = (const float4*)(h + (size_t)node * D_HID);
    float4 v0 = __ldg(hp + lane);
    float4 v1 = __ldg(hp + lane + 32);
    float4 a0 = make_float4(v0.x * di, v0.y * di, v0.z * di, v0.w * di);
    float4 a1 = make_float4(v1.x * di, v1.y * di, v1.z * di, v1.w * di);

    int e0 = off[node];
    int e1 = (node + 1 < n) ? off[node + 1] : E;
    for (int e = e0; e < e1; e++) {
        int s = srcsort[e];
        float ds = __ldg(dinv + s);
        const float4* sp = (const float4*)(h + (size_t)s * D_HID);
        float4 u0 = __ldg(sp + lane);
        float4 u1 = __ldg(sp + lane + 32);
        a0.x = fmaf(u0.x, ds, a0.x); a0.y = fmaf(u0.y, ds, a0.y);
        a0.z = fmaf(u0.z, ds, a0.z); a0.w = fmaf(u0.w, ds, a0.w);
        a1.x = fmaf(u1.x, ds, a1.x); a1.y = fmaf(u1.y, ds, a1.y);
        a1.z = fmaf(u1.z, ds, a1.z); a1.w = fmaf(u1.w, ds, a1.w);
    }

    const float4* bb = (const float4*)b1;
    float4 c0 = __ldg(bb + lane);
    float4 c1 = __ldg(bb + lane + 32);
    float4 r0, r1;
    r0.x = fmaxf(fmaf(a0.x, di, c0.x), 0.0f);
    r0.y = fmaxf(fmaf(a0.y, di, c0.y), 0.0f);
    r0.z = fmaxf(fmaf(a0.z, di, c0.z), 0.0f);
    r0.w = fmaxf(fmaf(a0.w, di, c0.w), 0.0f);
    r1.x = fmaxf(fmaf(a1.x, di, c1.x), 0.0f);
    r1.y = fmaxf(fmaf(a1.y, di, c1.y), 0.0f);
    r1.z = fmaxf(fmaf(a1.z, di, c1.z), 0.0f);
    r1.w = fmaxf(fmaf(a1.w, di, c1.w), 0.0f);

    uint32_t h0a, l0a, h0b, l0b, h1a, l1a, h1b, l1b;
    split2_bf16(make_float2(r0.x, r0.y), h0a, l0a);
    split2_bf16(make_float2(r0.z, r0.w), h0b, l0b);
    split2_bf16(make_float2(r1.x, r1.y), h1a, l1a);
    split2_bf16(make_float2(r1.z, r1.w), h1b, l1b);
    uint2* ophi = (uint2*)(a1hi + (size_t)node * KW);
    uint2* oplo = (uint2*)(a1lo + (size_t)node * KW);
    ophi[lane]      = make_uint2(h0a, h0b);
    ophi[lane + 32] = make_uint2(h1a, h1b);
    oplo[lane]      = make_uint2(l0a, l0b);
    oplo[lane + 32] = make_uint2(l1a, l1b);
}

// ====== layer-2 aggregate ======
__global__ void agg2_kernel(const float* __restrict__ h,
                            const int* __restrict__ srcsort,
                            const int* __restrict__ off,
                            const float* __restrict__ dinv,
                            const float* __restrict__ b2,
                            float* __restrict__ out, int n, int E) {
    int node = blockIdx.x * (blockDim.x >> 5) + (threadIdx.x >> 5);
    if (node >= n) return;
    int lane = threadIdx.x & 31;

    float di = dinv[node];
    const float2* hp = (const float2*)(h + (size_t)node * D_CLS);
    float2 u = __ldg(hp + lane);
    float2 a = make_float2(u.x * di, u.y * di);

    int e0 = off[node];
    int e1 = (node + 1 < n) ? off[node + 1] : E;
    for (int e = e0; e < e1; e++) {
        int s = srcsort[e];
        float ds = __ldg(dinv + s);
        float2 v = __ldg(((const float2*)(h + (size_t)s * D_CLS)) + lane);
        a.x = fmaf(v.x, ds, a.x);
        a.y = fmaf(v.y, ds, a.y);
    }

    float v0 = fmaf(a.x, di, __ldg(b2 + 2 * lane));
    float v1 = fmaf(a.y, di, __ldg(b2 + 2 * lane + 1));

    float m = fmaxf(v0, v1);
#pragma unroll
    for (int o = 16; o > 0; o >>= 1) m = fmaxf(m, __shfl_xor_sync(0xFFFFFFFFu, m, o));
    float s = __expf(v0 - m) + __expf(v1 - m);
#pragma unroll
    for (int o = 16; o > 0; o >>= 1) s += __shfl_xor_sync(0xFFFFFFFFu, s, o);
    float lse = m + __logf(s);

    float2* op = (float2*)(out + (size_t)node * D_CLS);
    op[lane] = make_float2(v0 - lse, v1 - lse);
}

extern "C" void kernel_launch(void* const* d_in, const int* in_sizes, int n_in,
                              void* d_out, int out_size) {
    const float* x   = (const float*)d_in[0];
    const int*   ei  = (const int*)d_in[1];   // JAX int64 request silently -> int32
    const float* W1  = (const float*)d_in[2];
    const float* b1  = (const float*)d_in[3];
    const float* W2  = (const float*)d_in[4];
    const float* b2  = (const float*)d_in[5];
    float*       out = (float*)d_out;

    const int n = in_sizes[0] / D_IN;
    const int E = in_sizes[1] / 2;
    const int* src = ei;
    const int* dst = ei + E;

    float *h1, *h2, *dinv;
    uint32_t *xhi, *xlo, *a1hi, *a1lo, *w1hi, *w1lo, *w2hi, *w2lo;
    int *cnt, *off, *cur, *srcsort, *bsum, *boff;
    cudaGetSymbolAddress((void**)&h1,   g_h1);
    cudaGetSymbolAddress((void**)&h2,   g_h2);
    cudaGetSymbolAddress((void**)&xhi,  g_xhi);
    cudaGetSymbolAddress((void**)&xlo,  g_xlo);
    cudaGetSymbolAddress((void**)&a1hi, g_a1hi);
    cudaGetSymbolAddress((void**)&a1lo, g_a1lo);
    cudaGetSymbolAddress((void**)&w1hi, g_w1hi);
    cudaGetSymbolAddress((void**)&w1lo, g_w1lo);
    cudaGetSymbolAddress((void**)&w2hi, g_w2hi);
    cudaGetSymbolAddress((void**)&w2lo, g_w2lo);
    cudaGetSymbolAddress((void**)&dinv, g_dinv);
    cudaGetSymbolAddress((void**)&cnt,  g_cnt);
    cudaGetSymbolAddress((void**)&off,  g_off);
    cudaGetSymbolAddress((void**)&cur,  g_cur);
    cudaGetSymbolAddress((void**)&srcsort, g_srcsort);
    cudaGetSymbolAddress((void**)&bsum, g_bsum);
    cudaGetSymbolAddress((void**)&boff, g_boff);

    const int NB = (n + 255) / 256;   // <= 1024
    const int MB = (n + 127) / 128;
    const long nwords = (long)n * KW;

    // 3-stage swizzled pipeline: 72KB dynamic smem (3 CTAs/SM)
    const int SMEM_GEMM = 3 * 24576;   // 73728
    cudaFuncSetAttribute(gemm_bf16x3, cudaFuncAttributeMaxDynamicSharedMemorySize, SMEM_GEMM);

    // 1: split x (+ zero cnt), 2: split weights, 3: degree count
    split_x<<<2048, 256>>>(x, xhi, xlo, cnt, n, nwords);
    split_w<<<(D_HID * KW + D_CLS * KW + 255) / 256, 256>>>(W1, W2, w1hi, w1lo, w2hi, w2lo);
    count_dst<<<(E + 255) / 256, 256>>>(dst, cnt, E);

    // 4: GEMM1 (profiler capture slot): h1 = x @ W1
    gemm_bf16x3<<<dim3(D_HID / 64, MB), 256, SMEM_GEMM>>>(xhi, xlo, w1hi, w1lo, h1, n, D_HID);

    // CSR (+ dinv fused into scan_final)
    block_sums <<<NB, 256>>>(cnt, bsum, n);
    scan_bsums <<<1, 1024>>>(bsum, boff, NB);
    scan_final <<<NB, 256>>>(cnt, boff, off, cur, dinv, n);
    place_edges<<<(E + 255) / 256, 256>>>(src, dst, cur, srcsort, E);

    // agg1: normalize+aggregate+bias+relu, emit split bf16
    agg1_kernel<<<(n + 7) / 8, 256>>>(h1, srcsort, off, dinv, b1, a1hi, a1lo, n, E);

    // GEMM2: h2 = agg1 @ W2
    gemm_bf16x3<<<dim3(D_CLS / 64, MB), 256, SMEM_GEMM>>>(a1hi, a1lo, w2hi, w2lo, h2, n, D_CLS);

    // agg2: normalize+aggregate+bias+log_softmax
    agg2_kernel<<<(n + 7) / 8, 256>>>(h2, srcsort, off, dinv, b2, out, n, E);
}